// round 7
// baseline (speedup 1.0000x reference)
#include <cuda_runtime.h>
#include <cuda_bf16.h>
#include <math.h>

#define BB    128      // batch
#define TAPE  100000
#define NN    50000
#define FF    32
#define NTILE 32

// Scratch: tape transposed to (TAPE, B) so a b-column is 128 contiguous floats.
// 100000 * 128 * 4B = 51.2 MB static device array (allowed; no allocation).
__device__ float g_tapeT[(size_t)TAPE * BB];

// ---------------------------------------------------------------------------
// Kernel 1: tiled transpose tape (B, TAPE) -> g_tapeT (TAPE, B)
// ---------------------------------------------------------------------------
__global__ void transpose_kernel(const float* __restrict__ tape) {
    __shared__ float tile[32][33];
    int i0 = blockIdx.x * 32;   // TAPE coordinate
    int b0 = blockIdx.y * 32;   // B coordinate
    int tx = threadIdx.x;       // 0..31
    int ty = threadIdx.y;       // 0..7
#pragma unroll
    for (int r = 0; r < 32; r += 8) {
        tile[ty + r][tx] = tape[(size_t)(b0 + ty + r) * TAPE + i0 + tx];
    }
    __syncthreads();
#pragma unroll
    for (int r = 0; r < 32; r += 8) {
        g_tapeT[(size_t)(i0 + ty + r) * BB + b0 + tx] = tile[tx][ty + r];
    }
}

// ---------------------------------------------------------------------------
// Kernel 2: fused gather-GEMV + activation + transposed store to out[:, 0:N)
// One block = 128 threads (thread = b), NTILE n-values per block.
// Gathers tapeT[idx*128 + b]: warp reads 128 contiguous bytes -> coalesced.
// Results transposed in smem so the out writes are coalesced along n.
// ---------------------------------------------------------------------------
__global__ void __launch_bounds__(128) gemv_kernel(
    const float* __restrict__ weights,
    const float* __restrict__ bias,
    const int*   __restrict__ in_idx,
    const int*   __restrict__ act,
    float*       __restrict__ out)
{
    __shared__ int   s_idx[NTILE * FF];
    __shared__ float s_w  [NTILE * FF];
    __shared__ float s_b  [NTILE];
    __shared__ int   s_a  [NTILE];
    __shared__ float s_t  [NTILE * 129];   // padded transpose buffer

    const int tid = threadIdx.x;           // == b
    const int n0  = blockIdx.x * NTILE;
    const int nmax = (NN - n0 < NTILE) ? (NN - n0) : NTILE;

    // stage indices / weights / bias / act type for this n-tile
    for (int k = tid; k < nmax * FF; k += 128) {
        s_idx[k] = in_idx[(size_t)n0 * FF + k];
        s_w[k]   = weights[(size_t)n0 * FF + k];
    }
    if (tid < nmax) {
        s_b[tid] = bias[n0 + tid];
        s_a[tid] = act[n0 + tid];
    }
    __syncthreads();

    const float* __restrict__ tT = g_tapeT;

    for (int nn = 0; nn < nmax; nn++) {
        float acc = s_b[nn];
#pragma unroll
        for (int f = 0; f < FF; f++) {
            int idx = s_idx[nn * FF + f];
            acc = fmaf(tT[(size_t)idx * BB + tid], s_w[nn * FF + f], acc);
        }
        float v = (s_a[nn] == 0) ? fmaxf(acc, 0.0f) : tanhf(acc);
        s_t[nn * 129 + tid] = v;
    }
    __syncthreads();

    // transposed write: warp w, lane l writes out[b' = j*4+w][n0 + l]
    const int lane = tid & 31;
    const int w    = tid >> 5;
    if (n0 + lane < NN) {
#pragma unroll 4
        for (int j = 0; j < 32; j++) {
            int bb = j * 4 + w;
            if (lane < nmax)
                out[(size_t)bb * TAPE + n0 + lane] = s_t[lane * 129 + bb];
        }
    }
}

// ---------------------------------------------------------------------------
// Kernel 3: float4 copy of the untouched region out[:, N:TAPE) = tape[:, N:TAPE)
// (TAPE - N) = 50000 -> 12500 float4 per row; offsets are 16B aligned.
// ---------------------------------------------------------------------------
__global__ void copy_kernel(const float* __restrict__ tape, float* __restrict__ out) {
    const int per_row = (TAPE - NN) / 4;                 // 12500
    size_t gid = (size_t)blockIdx.x * blockDim.x + threadIdx.x;
    if (gid >= (size_t)BB * per_row) return;
    int b = (int)(gid / per_row);
    int c = (int)(gid % per_row);
    const float4* src = (const float4*)(tape + (size_t)b * TAPE + NN);
    float4*       dst = (float4*)(out  + (size_t)b * TAPE + NN);
    dst[c] = src[c];
}

// ---------------------------------------------------------------------------
// Inputs (metadata order): tape f32, weights f32, bias f32,
//                          input_indices i32, output_indices i32, act_type i32
// output_indices == arange(N) by construction -> dense column-block scatter.
// ---------------------------------------------------------------------------
extern "C" void kernel_launch(void* const* d_in, const int* in_sizes, int n_in,
                              void* d_out, int out_size) {
    const float* tape    = (const float*)d_in[0];
    const float* weights = (const float*)d_in[1];
    const float* bias    = (const float*)d_in[2];
    const int*   in_idx  = (const int*)d_in[3];
    // d_in[4] = output_indices (arange, unused)
    const int*   act     = (const int*)d_in[5];
    float*       out     = (float*)d_out;

    // 1) transpose tape -> g_tapeT
    dim3 tgrid(TAPE / 32, BB / 32);
    dim3 tblock(32, 8);
    transpose_kernel<<<tgrid, tblock>>>(tape);

    // 2) fused gather-GEMV + activation + write out[:, 0:N)
    int gblocks = (NN + NTILE - 1) / NTILE;   // 1563
    gemv_kernel<<<gblocks, 128>>>(weights, bias, in_idx, act, out);

    // 3) copy out[:, N:TAPE)
    size_t total4 = (size_t)BB * ((TAPE - NN) / 4);
    int cblocks = (int)((total4 + 255) / 256);
    copy_kernel<<<cblocks, 256>>>(tape, out);
}

// round 8
// speedup vs baseline: 1.6783x; 1.6783x over previous
#include <cuda_runtime.h>
#include <cuda_fp16.h>
#include <math.h>

#define BB    128      // batch
#define TAPE  100000
#define NN    50000
#define FF    32
#define NTILE 32

// Transposed tape in fp16: (TAPE, B). 100000*128*2B = 25.6 MB static scratch.
// Fits comfortably in the 126MB L2, so gathers are L2 hits after first touch.
__device__ __half g_tapeTh[(size_t)TAPE * BB];

// ---------------------------------------------------------------------------
// Kernel 1: transpose tape (B, TAPE) f32 -> g_tapeTh (TAPE, B) fp16
// Tile: 32 b-rows x 128 i-cols, float4 global reads, half global writes.
// ---------------------------------------------------------------------------
__global__ void __launch_bounds__(256) transpose_kernel(const float* __restrict__ tape) {
    __shared__ float tile[32][129];   // [b][i], pad 129 -> conflict-free both phases
    const int i0 = blockIdx.x * 128;
    const int b0 = blockIdx.y * 32;
    const int tx = threadIdx.x;       // 0..31 (i/4 within tile on read)
    const int ty = threadIdx.y;       // 0..7
    const int tid = ty * 32 + tx;
    const int wp  = tid >> 5;         // 0..7
    const int ln  = tid & 31;

    // read: 32 b-rows, each row 128 floats via float4
#pragma unroll
    for (int r = 0; r < 32; r += 8) {
        int gi = i0 + tx * 4;
        if (gi < TAPE) {
            float4 v = *reinterpret_cast<const float4*>(
                tape + (size_t)(b0 + ty + r) * TAPE + gi);
            tile[ty + r][tx * 4 + 0] = v.x;
            tile[ty + r][tx * 4 + 1] = v.y;
            tile[ty + r][tx * 4 + 2] = v.z;
            tile[ty + r][tx * 4 + 3] = v.w;
        }
    }
    __syncthreads();

    // write: one warp per i-row, lanes cover 32 b (64B coalesced half writes)
#pragma unroll
    for (int rr = 0; rr < 128; rr += 8) {
        int il = rr + wp;
        int gi = i0 + il;
        if (gi < TAPE)
            g_tapeTh[(size_t)gi * BB + b0 + ln] = __float2half(tile[ln][il]);
    }
}

// ---------------------------------------------------------------------------
// Kernel 2: fused gather-GEMV + activation + transposed store to out[:, 0:N)
// Block = 128 threads = 4 warps, NTILE n-values per block.
// One warp per n: lane loads uint2 (4 fp16 b-values) -> 1 LDG.64 covers 128 b.
// ---------------------------------------------------------------------------
__global__ void __launch_bounds__(128) gemv_kernel(
    const float* __restrict__ weights,
    const float* __restrict__ bias,
    const int*   __restrict__ in_idx,
    const int*   __restrict__ act,
    float*       __restrict__ out)
{
    __shared__ int   s_idx[NTILE * FF];
    __shared__ float s_w  [NTILE * FF];
    __shared__ float s_b  [NTILE];
    __shared__ int   s_a  [NTILE];
    __shared__ float s_t  [NTILE * 133];   // [n][b], pad 133 -> conflict-free

    const int tid  = threadIdx.x;
    const int lane = tid & 31;
    const int wrp  = tid >> 5;             // 0..3
    const int n0   = blockIdx.x * NTILE;
    const int nmax = (NN - n0 < NTILE) ? (NN - n0) : NTILE;

    for (int k = tid; k < nmax * FF; k += 128) {
        s_idx[k] = in_idx[(size_t)n0 * FF + k];
        s_w[k]   = weights[(size_t)n0 * FF + k];
    }
    if (tid < nmax) {
        s_b[tid] = bias[n0 + tid];
        s_a[tid] = act[n0 + tid];
    }
    __syncthreads();

    const __half* __restrict__ tT = g_tapeTh;

    for (int nn = wrp; nn < nmax; nn += 4) {
        const float bv = s_b[nn];
        float a0 = bv, a1 = bv, a2 = bv, a3 = bv;
#pragma unroll
        for (int f = 0; f < FF; f++) {
            const int   idx = s_idx[nn * FF + f];
            const float wgt = s_w  [nn * FF + f];
            uint2 v = *reinterpret_cast<const uint2*>(tT + (size_t)idx * BB + lane * 4);
            __half2 h01 = *reinterpret_cast<__half2*>(&v.x);
            __half2 h23 = *reinterpret_cast<__half2*>(&v.y);
            float2 f01 = __half22float2(h01);
            float2 f23 = __half22float2(h23);
            a0 = fmaf(f01.x, wgt, a0);
            a1 = fmaf(f01.y, wgt, a1);
            a2 = fmaf(f23.x, wgt, a2);
            a3 = fmaf(f23.y, wgt, a3);
        }
        if (s_a[nn] == 0) {
            a0 = fmaxf(a0, 0.0f); a1 = fmaxf(a1, 0.0f);
            a2 = fmaxf(a2, 0.0f); a3 = fmaxf(a3, 0.0f);
        } else {
            a0 = tanhf(a0); a1 = tanhf(a1); a2 = tanhf(a2); a3 = tanhf(a3);
        }
        s_t[nn * 133 + lane * 4 + 0] = a0;
        s_t[nn * 133 + lane * 4 + 1] = a1;
        s_t[nn * 133 + lane * 4 + 2] = a2;
        s_t[nn * 133 + lane * 4 + 3] = a3;
    }
    __syncthreads();

    // coalesced transposed write: out[b][n0+lane]
    if (lane < nmax) {
#pragma unroll 4
        for (int j = 0; j < 32; j++) {
            int bb = j * 4 + wrp;
            out[(size_t)bb * TAPE + n0 + lane] = s_t[lane * 133 + bb];
        }
    }
}

// ---------------------------------------------------------------------------
// Kernel 3: float4 copy of untouched region out[:, N:TAPE) = tape[:, N:TAPE)
// ---------------------------------------------------------------------------
__global__ void copy_kernel(const float* __restrict__ tape, float* __restrict__ out) {
    const int per_row = (TAPE - NN) / 4;   // 12500
    size_t gid = (size_t)blockIdx.x * blockDim.x + threadIdx.x;
    if (gid >= (size_t)BB * per_row) return;
    int b = (int)(gid / per_row);
    int c = (int)(gid % per_row);
    const float4* src = (const float4*)(tape + (size_t)b * TAPE + NN);
    float4*       dst = (float4*)(out  + (size_t)b * TAPE + NN);
    dst[c] = src[c];
}

// ---------------------------------------------------------------------------
// Inputs (metadata order): tape f32, weights f32, bias f32,
//                          input_indices i32, output_indices i32, act_type i32
// output_indices == arange(N) -> dense column-block write.
// ---------------------------------------------------------------------------
extern "C" void kernel_launch(void* const* d_in, const int* in_sizes, int n_in,
                              void* d_out, int out_size) {
    const float* tape    = (const float*)d_in[0];
    const float* weights = (const float*)d_in[1];
    const float* bias    = (const float*)d_in[2];
    const int*   in_idx  = (const int*)d_in[3];
    const int*   act     = (const int*)d_in[5];
    float*       out     = (float*)d_out;

    dim3 tgrid((TAPE + 127) / 128, BB / 32);   // (782, 4)
    dim3 tblock(32, 8);
    transpose_kernel<<<tgrid, tblock>>>(tape);

    int gblocks = (NN + NTILE - 1) / NTILE;    // 1563
    gemv_kernel<<<gblocks, 128>>>(weights, bias, in_idx, act, out);

    size_t total4 = (size_t)BB * ((TAPE - NN) / 4);
    int cblocks = (int)((total4 + 255) / 256);
    copy_kernel<<<cblocks, 256>>>(tape, out);
}

// round 9
// speedup vs baseline: 1.6800x; 1.0010x over previous
#include <cuda_runtime.h>
#include <cuda_fp16.h>
#include <math.h>

#define BB    128      // batch
#define TAPE  100000
#define NN    50000
#define FF    32
#define NTILE 32

// Transposed tape in fp16: (TAPE, B). 100000*128*2B = 25.6 MB static scratch.
// Fits comfortably in the 126MB L2, so gathers are L2 hits after first touch.
__device__ __half g_tapeTh[(size_t)TAPE * BB];

// ---------------------------------------------------------------------------
// Kernel 1: transpose tape (B, TAPE) f32 -> g_tapeTh (TAPE, B) fp16
// Tile: 32 b-rows x 128 i-cols, float4 global reads, half global writes.
// ---------------------------------------------------------------------------
__global__ void __launch_bounds__(256) transpose_kernel(const float* __restrict__ tape) {
    __shared__ float tile[32][129];   // [b][i], pad 129 -> conflict-free both phases
    const int i0 = blockIdx.x * 128;
    const int b0 = blockIdx.y * 32;
    const int tx = threadIdx.x;       // 0..31 (i/4 within tile on read)
    const int ty = threadIdx.y;       // 0..7
    const int tid = ty * 32 + tx;
    const int wp  = tid >> 5;         // 0..7
    const int ln  = tid & 31;

    // read: 32 b-rows, each row 128 floats via float4
#pragma unroll
    for (int r = 0; r < 32; r += 8) {
        int gi = i0 + tx * 4;
        if (gi < TAPE) {
            float4 v = *reinterpret_cast<const float4*>(
                tape + (size_t)(b0 + ty + r) * TAPE + gi);
            tile[ty + r][tx * 4 + 0] = v.x;
            tile[ty + r][tx * 4 + 1] = v.y;
            tile[ty + r][tx * 4 + 2] = v.z;
            tile[ty + r][tx * 4 + 3] = v.w;
        }
    }
    __syncthreads();

    // write: one warp per i-row, lanes cover 32 b (64B coalesced half writes)
#pragma unroll
    for (int rr = 0; rr < 128; rr += 8) {
        int il = rr + wp;
        int gi = i0 + il;
        if (gi < TAPE)
            g_tapeTh[(size_t)gi * BB + b0 + ln] = __float2half(tile[ln][il]);
    }
}

// ---------------------------------------------------------------------------
// Kernel 2: fused gather-GEMV + activation + transposed store to out[:, 0:N)
// Block = 128 threads = 4 warps, NTILE n-values per block.
// One warp per n: lane loads uint2 (4 fp16 b-values) -> 1 LDG.64 covers 128 b.
// ---------------------------------------------------------------------------
__global__ void __launch_bounds__(128) gemv_kernel(
    const float* __restrict__ weights,
    const float* __restrict__ bias,
    const int*   __restrict__ in_idx,
    const int*   __restrict__ act,
    float*       __restrict__ out)
{
    __shared__ int   s_idx[NTILE * FF];
    __shared__ float s_w  [NTILE * FF];
    __shared__ float s_b  [NTILE];
    __shared__ int   s_a  [NTILE];
    __shared__ float s_t  [NTILE * 133];   // [n][b], pad 133 -> conflict-free

    const int tid  = threadIdx.x;
    const int lane = tid & 31;
    const int wrp  = tid >> 5;             // 0..3
    const int n0   = blockIdx.x * NTILE;
    const int nmax = (NN - n0 < NTILE) ? (NN - n0) : NTILE;

    for (int k = tid; k < nmax * FF; k += 128) {
        s_idx[k] = in_idx[(size_t)n0 * FF + k];
        s_w[k]   = weights[(size_t)n0 * FF + k];
    }
    if (tid < nmax) {
        s_b[tid] = bias[n0 + tid];
        s_a[tid] = act[n0 + tid];
    }
    __syncthreads();

    const __half* __restrict__ tT = g_tapeTh;

    for (int nn = wrp; nn < nmax; nn += 4) {
        const float bv = s_b[nn];
        float a0 = bv, a1 = bv, a2 = bv, a3 = bv;
#pragma unroll
        for (int f = 0; f < FF; f++) {
            const int   idx = s_idx[nn * FF + f];
            const float wgt = s_w  [nn * FF + f];
            uint2 v = *reinterpret_cast<const uint2*>(tT + (size_t)idx * BB + lane * 4);
            __half2 h01 = *reinterpret_cast<__half2*>(&v.x);
            __half2 h23 = *reinterpret_cast<__half2*>(&v.y);
            float2 f01 = __half22float2(h01);
            float2 f23 = __half22float2(h23);
            a0 = fmaf(f01.x, wgt, a0);
            a1 = fmaf(f01.y, wgt, a1);
            a2 = fmaf(f23.x, wgt, a2);
            a3 = fmaf(f23.y, wgt, a3);
        }
        if (s_a[nn] == 0) {
            a0 = fmaxf(a0, 0.0f); a1 = fmaxf(a1, 0.0f);
            a2 = fmaxf(a2, 0.0f); a3 = fmaxf(a3, 0.0f);
        } else {
            a0 = tanhf(a0); a1 = tanhf(a1); a2 = tanhf(a2); a3 = tanhf(a3);
        }
        s_t[nn * 133 + lane * 4 + 0] = a0;
        s_t[nn * 133 + lane * 4 + 1] = a1;
        s_t[nn * 133 + lane * 4 + 2] = a2;
        s_t[nn * 133 + lane * 4 + 3] = a3;
    }
    __syncthreads();

    // coalesced transposed write: out[b][n0+lane]
    if (lane < nmax) {
#pragma unroll 4
        for (int j = 0; j < 32; j++) {
            int bb = j * 4 + wrp;
            out[(size_t)bb * TAPE + n0 + lane] = s_t[lane * 133 + bb];
        }
    }
}

// ---------------------------------------------------------------------------
// Kernel 3: float4 copy of untouched region out[:, N:TAPE) = tape[:, N:TAPE)
// ---------------------------------------------------------------------------
__global__ void copy_kernel(const float* __restrict__ tape, float* __restrict__ out) {
    const int per_row = (TAPE - NN) / 4;   // 12500
    size_t gid = (size_t)blockIdx.x * blockDim.x + threadIdx.x;
    if (gid >= (size_t)BB * per_row) return;
    int b = (int)(gid / per_row);
    int c = (int)(gid % per_row);
    const float4* src = (const float4*)(tape + (size_t)b * TAPE + NN);
    float4*       dst = (float4*)(out  + (size_t)b * TAPE + NN);
    dst[c] = src[c];
}

// ---------------------------------------------------------------------------
// Inputs (metadata order): tape f32, weights f32, bias f32,
//                          input_indices i32, output_indices i32, act_type i32
// output_indices == arange(N) -> dense column-block write.
// ---------------------------------------------------------------------------
extern "C" void kernel_launch(void* const* d_in, const int* in_sizes, int n_in,
                              void* d_out, int out_size) {
    const float* tape    = (const float*)d_in[0];
    const float* weights = (const float*)d_in[1];
    const float* bias    = (const float*)d_in[2];
    const int*   in_idx  = (const int*)d_in[3];
    const int*   act     = (const int*)d_in[5];
    float*       out     = (float*)d_out;

    dim3 tgrid((TAPE + 127) / 128, BB / 32);   // (782, 4)
    dim3 tblock(32, 8);
    transpose_kernel<<<tgrid, tblock>>>(tape);

    int gblocks = (NN + NTILE - 1) / NTILE;    // 1563
    gemv_kernel<<<gblocks, 128>>>(weights, bias, in_idx, act, out);

    size_t total4 = (size_t)BB * ((TAPE - NN) / 4);
    int cblocks = (int)((total4 + 255) / 256);
    copy_kernel<<<cblocks, 256>>>(tape, out);
}

// round 10
// speedup vs baseline: 1.8803x; 1.1192x over previous
#include <cuda_runtime.h>
#include <cuda_fp16.h>
#include <math.h>

#define BB    128      // batch
#define TAPE  100000
#define NN    50000
#define FF    32
#define NTILE 32

// Transposed tape in fp16: (TAPE, B). 25.6 MB static scratch -> L2-resident.
__device__ __align__(16) __half g_tapeTh[(size_t)TAPE * BB];

__device__ __forceinline__ float fast_tanh(float x) {
    float y;
    asm("tanh.approx.f32 %0, %1;" : "=f"(y) : "f"(x));
    return y;
}

// ---------------------------------------------------------------------------
// Kernel 1: fused transpose + passthrough copy.
//   reads tape (B, TAPE) f32 once;
//   writes g_tapeTh (TAPE, B) fp16;
//   and for gi >= NN also writes the float4 straight to out (copy region).
// Tile: 32 b x 128 i. Write phase: half2 stores, 2 i-rows per warp iteration.
// Bank check (pad 129): lane ln reads tile[2k][il] with k=ln&15, il differs by
// parity of ln>>4 -> even/odd bank split across half-warps => conflict-free.
// ---------------------------------------------------------------------------
__global__ void __launch_bounds__(256) transpose_copy_kernel(
    const float* __restrict__ tape, float* __restrict__ out)
{
    __shared__ float tile[32][129];
    const int i0  = blockIdx.x * 128;
    const int b0  = blockIdx.y * 32;
    const int tx  = threadIdx.x;      // 0..31
    const int ty  = threadIdx.y;      // 0..7
    const int tid = ty * 32 + tx;
    const int wp  = tid >> 5;         // 0..7
    const int ln  = tid & 31;

    // read phase: float4 loads along i; fused copy-out for gi >= NN
#pragma unroll
    for (int r = 0; r < 32; r += 8) {
        const int b  = b0 + ty + r;
        const int gi = i0 + tx * 4;
        if (gi < TAPE) {
            float4 v = *reinterpret_cast<const float4*>(tape + (size_t)b * TAPE + gi);
            tile[ty + r][tx * 4 + 0] = v.x;
            tile[ty + r][tx * 4 + 1] = v.y;
            tile[ty + r][tx * 4 + 2] = v.z;
            tile[ty + r][tx * 4 + 3] = v.w;
            if (gi >= NN)   // NN and i0 are multiples of 4 -> whole-float4 granularity
                *reinterpret_cast<float4*>(out + (size_t)b * TAPE + gi) = v;
        }
    }
    __syncthreads();

    // write phase: half2 (2 b-values per lane), 2 i-rows per warp iteration
    const int bq   = (ln & 15) * 2;   // 0,2,...,30
    const int isub = ln >> 4;         // 0 or 1
#pragma unroll
    for (int rr = 0; rr < 128; rr += 16) {
        const int il = rr + wp * 2 + isub;
        const int gi = i0 + il;
        if (gi < TAPE) {
            __half2 h = __floats2half2_rn(tile[bq][il], tile[bq + 1][il]);
            *reinterpret_cast<__half2*>(&g_tapeTh[(size_t)gi * BB + b0 + bq]) = h;
        }
    }
}

// ---------------------------------------------------------------------------
// Kernel 2: fused gather-GEMV + activation + transposed store to out[:, 0:N)
// Block = 128 threads = 4 warps, NTILE n-values per block.
// One warp per n: lane loads uint2 (4 fp16 b-values) -> 1 LDG.64 covers 128 b.
// ---------------------------------------------------------------------------
__global__ void __launch_bounds__(128) gemv_kernel(
    const float* __restrict__ weights,
    const float* __restrict__ bias,
    const int*   __restrict__ in_idx,
    const int*   __restrict__ act,
    float*       __restrict__ out)
{
    __shared__ int   s_idx[NTILE * FF];
    __shared__ float s_w  [NTILE * FF];
    __shared__ float s_b  [NTILE];
    __shared__ int   s_a  [NTILE];
    __shared__ float s_t  [NTILE * 133];   // [n][b], pad 133 -> conflict-free

    const int tid  = threadIdx.x;
    const int lane = tid & 31;
    const int wrp  = tid >> 5;             // 0..3
    const int n0   = blockIdx.x * NTILE;
    const int nmax = (NN - n0 < NTILE) ? (NN - n0) : NTILE;

    for (int k = tid; k < nmax * FF; k += 128) {
        s_idx[k] = in_idx[(size_t)n0 * FF + k];
        s_w[k]   = weights[(size_t)n0 * FF + k];
    }
    if (tid < nmax) {
        s_b[tid] = bias[n0 + tid];
        s_a[tid] = act[n0 + tid];
    }
    __syncthreads();

    const __half* __restrict__ tT = g_tapeTh;

    for (int nn = wrp; nn < nmax; nn += 4) {
        const float bv = s_b[nn];
        float a0 = bv, a1 = bv, a2 = bv, a3 = bv;
#pragma unroll
        for (int f = 0; f < FF; f++) {
            const int   idx = s_idx[nn * FF + f];
            const float wgt = s_w  [nn * FF + f];
            uint2 v = *reinterpret_cast<const uint2*>(tT + (size_t)idx * BB + lane * 4);
            __half2 h01 = *reinterpret_cast<__half2*>(&v.x);
            __half2 h23 = *reinterpret_cast<__half2*>(&v.y);
            float2 f01 = __half22float2(h01);
            float2 f23 = __half22float2(h23);
            a0 = fmaf(f01.x, wgt, a0);
            a1 = fmaf(f01.y, wgt, a1);
            a2 = fmaf(f23.x, wgt, a2);
            a3 = fmaf(f23.y, wgt, a3);
        }
        if (s_a[nn] == 0) {
            a0 = fmaxf(a0, 0.0f); a1 = fmaxf(a1, 0.0f);
            a2 = fmaxf(a2, 0.0f); a3 = fmaxf(a3, 0.0f);
        } else {
            a0 = fast_tanh(a0); a1 = fast_tanh(a1);
            a2 = fast_tanh(a2); a3 = fast_tanh(a3);
        }
        s_t[nn * 133 + lane * 4 + 0] = a0;
        s_t[nn * 133 + lane * 4 + 1] = a1;
        s_t[nn * 133 + lane * 4 + 2] = a2;
        s_t[nn * 133 + lane * 4 + 3] = a3;
    }
    __syncthreads();

    // coalesced transposed write: out[b][n0+lane]
    if (lane < nmax) {
#pragma unroll 4
        for (int j = 0; j < 32; j++) {
            int bb = j * 4 + wrp;
            out[(size_t)bb * TAPE + n0 + lane] = s_t[lane * 133 + bb];
        }
    }
}

// ---------------------------------------------------------------------------
// Inputs (metadata order): tape f32, weights f32, bias f32,
//                          input_indices i32, output_indices i32, act_type i32
// output_indices == arange(N) -> dense column-block write.
// ---------------------------------------------------------------------------
extern "C" void kernel_launch(void* const* d_in, const int* in_sizes, int n_in,
                              void* d_out, int out_size) {
    const float* tape    = (const float*)d_in[0];
    const float* weights = (const float*)d_in[1];
    const float* bias    = (const float*)d_in[2];
    const int*   in_idx  = (const int*)d_in[3];
    const int*   act     = (const int*)d_in[5];
    float*       out     = (float*)d_out;

    // 1) fused transpose (f32 -> fp16, (B,TAPE)->(TAPE,B)) + copy of out[:, N:)
    dim3 tgrid((TAPE + 127) / 128, BB / 32);   // (782, 4)
    dim3 tblock(32, 8);
    transpose_copy_kernel<<<tgrid, tblock>>>(tape, out);

    // 2) fused gather-GEMV + activation + write out[:, 0:N)
    int gblocks = (NN + NTILE - 1) / NTILE;    // 1563
    gemv_kernel<<<gblocks, 128>>>(weights, bias, in_idx, act, out);
}